// round 12
// baseline (speedup 1.0000x reference)
#include <cuda_runtime.h>
#include <cuda_fp16.h>
#include <cstdint>
#include <cstddef>

#define NB   64
#define NIC  128
#define NOC  256
#define NHW  56
#define NDG  4
#define HW2  (NHW*NHW)

#define NTHREADS 256
#define ROWS_PER_CTA 4
#define BROWS 348                  // (4 out rows + 2 halo) x 58 w-positions

// ---------------- smem layout (dynamic, 151 KB, 1 CTA/SM) ----------------
#define SM_BH   0                  // 348 * 256 B = 89088
#define SM_A0   89088              // 32 KB
#define SM_A1   121856             // 32 KB
#define SMEM_TOTAL 154624

// Pre-swizzled fp16 weights: per (d, octile, tap): 16384 halfs (32 KB)
__device__ __align__(16) __half g_w2[NDG * 2 * 9 * 16384];

// ---------------- ptx helpers (baseline ISA only) ----------------
__device__ __forceinline__ uint32_t smem_u32(const void* p) {
    uint32_t a;
    asm("{ .reg .u64 t; cvta.to.shared.u64 t, %1; cvt.u32.u64 %0, t; }"
        : "=r"(a) : "l"(p));
    return a;
}
__device__ __forceinline__ void ldsm_x4(uint32_t* r, uint32_t addr) {
    asm volatile("ldmatrix.sync.aligned.m8n8.x4.shared.b16 {%0,%1,%2,%3}, [%4];"
                 : "=r"(r[0]), "=r"(r[1]), "=r"(r[2]), "=r"(r[3]) : "r"(addr));
}
__device__ __forceinline__ void ldsm_x2(uint32_t* r, uint32_t addr) {
    asm volatile("ldmatrix.sync.aligned.m8n8.x2.shared.b16 {%0,%1}, [%2];"
                 : "=r"(r[0]), "=r"(r[1]) : "r"(addr));
}
__device__ __forceinline__ void cp_async16(uint32_t saddr, const void* gptr) {
    asm volatile("cp.async.cg.shared.global [%0], [%1], 16;"
                 :: "r"(saddr), "l"(gptr) : "memory");
}
#define CP_COMMIT() asm volatile("cp.async.commit_group;" ::: "memory")
#define CP_WAIT0()  asm volatile("cp.async.wait_group 0;" ::: "memory")

#define MMA_FP16(c, a, b)                                                     \
    asm volatile(                                                             \
        "mma.sync.aligned.m16n8k16.row.col.f32.f16.f16.f32 "                  \
        "{%0,%1,%2,%3},{%4,%5,%6,%7},{%8,%9},{%0,%1,%2,%3};"                  \
        : "+f"((c)[0]), "+f"((c)[1]), "+f"((c)[2]), "+f"((c)[3])              \
        : "r"((a)[0]), "r"((a)[1]), "r"((a)[2]), "r"((a)[3]),                 \
          "r"((b)[0]), "r"((b)[1]))

// ---------------------------------------------------------------------------
// Prep: masked weights -> fp16, XOR-swizzled smem image
// byte(oc, ic) = oc*256 + ((ic*2) ^ ((oc&7)<<4))
// ---------------------------------------------------------------------------
__global__ void prep_weights_kernel(const float* __restrict__ base,
                                    const float* __restrict__ mask) {
    int e = blockIdx.x * blockDim.x + threadIdx.x;
    const int total = NDG * 2 * 9 * 128 * 128;
    if (e >= total) return;
    int ic  = e % 128;
    int t2  = e / 128;
    int oc  = t2 % 128;
    int t3  = t2 / 128;
    int tap = t3 % 9;
    int t4  = t3 / 9;
    int oct = t4 % 2;
    int d   = t4 / 2;

    float w = base[((size_t)(oct * 128 + oc) * 128 + ic) * 9 + tap] *
              mask[((size_t)d * 128 + ic) * 9 + tap];

    uint32_t byte = (uint32_t)(oc * 256 + ((ic * 2) ^ ((oc & 7) << 4)));
    size_t slab = (size_t)((d * 2 + oct) * 9 + tap) * 16384;
    g_w2[slab + (byte >> 1)] = __float2half(w);
}

// ---------------------------------------------------------------------------
// CTA = (4-row block, octile 128, b). 256 threads = 8 warps: 2 M-warps
// (M64 = 4 m-tiles) x 4 N-warps (1 output row, N=56). Single-pass fp16.
// ---------------------------------------------------------------------------
__global__ __launch_bounds__(NTHREADS, 1)
void adaconv_mma_kernel(const float* __restrict__ x,
                        const int*   __restrict__ label,
                        float*       __restrict__ out) {
    extern __shared__ char smem[];
    const uint32_t sb = smem_u32(smem);

    const int tid  = threadIdx.x;
    const int wid  = tid >> 5;
    const int lane = tid & 31;
    const int warp_m = wid & 1;       // oc tile of 64
    const int warp_n = wid >> 1;      // output row (0..3)

    const int hb  = blockIdx.x;       // 0..13
    const int oct = blockIdx.y;       // 0..1
    const int b   = blockIdx.z;       // 0..63
    const int h0  = hb * ROWS_PER_CTA;

    int d = label[b];
    d = (d < 0) ? 0 : (d > NDG - 1 ? NDG - 1 : d);

    const float* __restrict__ xg = x + (size_t)b * NIC * HW2;
    const char* __restrict__ wbase =
        (const char*)(g_w2 + (size_t)((d * 2 + oct) * 9) * 16384);

    // ---- prologue: A(0) -> buf0 (2048 x 16B / 256 threads) ----
    {
#pragma unroll
        for (int j = 0; j < 8; ++j)
            cp_async16(sb + SM_A0 + tid * 16 + j * 4096, wbase + tid * 16 + j * 4096);
        CP_COMMIT();
    }

    // ---- build B once: 348 n-rows, each thread owns rows tid, tid+256 ----
    {
#pragma unroll
        for (int it = 0; it < 2; ++it) {
            int np = tid + it * 256;
            if (np < BROWS) {
                const int rowl = np / 58;
                const int wq   = np - rowl * 58;
                const int h_in = h0 - 1 + rowl;
                const int w_in = wq - 1;
                const bool inb = (h_in >= 0 && h_in < NHW && w_in >= 0 && w_in < NHW);
                const float* __restrict__ xp = xg + (size_t)h_in * NHW + w_in;
                const uint32_t brow = (uint32_t)(np * 256);
                const uint32_t bx   = (uint32_t)((np & 7) << 4);
#pragma unroll 8
                for (int icp = 0; icp < 64; ++icp) {
                    float v0 = 0.f, v1 = 0.f;
                    if (inb) {
                        v0 = xp[(size_t)(icp * 2) * HW2];
                        v1 = xp[(size_t)(icp * 2 + 1) * HW2];
                    }
                    __half h0b = __float2half(v0);
                    __half h1b = __float2half(v1);
                    uint32_t hw = (uint32_t)__half_as_ushort(h0b) |
                                  ((uint32_t)__half_as_ushort(h1b) << 16);
                    uint32_t byte = brow + (((uint32_t)(icp * 4)) ^ bx);
                    *(uint32_t*)(smem + SM_BH + byte) = hw;
                }
            }
        }
    }

    float acc[4][7][4];
#pragma unroll
    for (int mt = 0; mt < 4; ++mt)
#pragma unroll
        for (int nt = 0; nt < 7; ++nt)
#pragma unroll
            for (int q = 0; q < 4; ++q) acc[mt][nt][q] = 0.f;

    const int arow     = warp_m * 64 + (lane & 15);
    const uint32_t akb = (uint32_t)((lane >> 4) << 4);

    for (int tap = 0; tap < 9; ++tap) {
        const int dh = tap / 3, dw = tap % 3;
        const int nb = (warp_n + dh) * 58 + dw;
        const uint32_t ab = sb + ((tap & 1) ? SM_A1 : SM_A0);

        CP_WAIT0();
        __syncthreads();   // A(tap) visible (+ B on tap 0); alt buf reads done

        if (tap < 8) {     // prefetch A(tap+1) into the other buffer
            const char* gsrc = wbase + (size_t)(tap + 1) * 32768;
            uint32_t dst = sb + ((tap & 1) ? SM_A0 : SM_A1);
#pragma unroll
            for (int j = 0; j < 8; ++j)
                cp_async16(dst + tid * 16 + j * 4096, gsrc + tid * 16 + j * 4096);
            CP_COMMIT();
        }

        // ---- 8 k-steps: load frags (single buffer), 28 mma ----
#pragma unroll 1
        for (int k = 0; k < 8; ++k) {
            const uint32_t kb = (uint32_t)(k * 32) + akb;

            uint32_t ah[4][4];
#pragma unroll
            for (int mt = 0; mt < 4; ++mt) {
                int r = arow + mt * 16;
                uint32_t off = (uint32_t)(r * 256) + (kb ^ (uint32_t)((r & 7) << 4));
                ldsm_x4(ah[mt], ab + off);
            }
            uint32_t bh[7][2];
#pragma unroll
            for (int p = 0; p < 3; ++p) {
                int n = nb + p * 16 + (lane & 15);
                uint32_t off = (uint32_t)(n * 256) + (kb ^ (uint32_t)((n & 7) << 4));
                uint32_t t[4];
                ldsm_x4(t, sb + SM_BH + off);
                bh[2 * p][0] = t[0]; bh[2 * p][1] = t[2];
                bh[2 * p + 1][0] = t[1]; bh[2 * p + 1][1] = t[3];
            }
            {
                int n = nb + 48 + (lane & 7);
                uint32_t kb2 = (uint32_t)(k * 32) + (uint32_t)(((lane >> 3) & 1) << 4);
                uint32_t off = (uint32_t)(n * 256) + (kb2 ^ (uint32_t)((n & 7) << 4));
                uint32_t t[2];
                ldsm_x2(t, sb + SM_BH + off);
                bh[6][0] = t[0]; bh[6][1] = t[1];
            }

#pragma unroll
            for (int mt = 0; mt < 4; ++mt)
#pragma unroll
                for (int nt = 0; nt < 7; ++nt) MMA_FP16(acc[mt][nt], ah[mt], bh[nt]);
        }
    }

    // ---- epilogue ----
    const int h = h0 + warp_n;
    const int col0 = (lane & 3) * 2;
    const int r0 = lane >> 2;
#pragma unroll
    for (int mt = 0; mt < 4; ++mt) {
        int ocb = oct * 128 + warp_m * 64 + mt * 16;
        float* __restrict__ o0 = out + ((size_t)b * NOC + ocb + r0) * HW2 + (size_t)h * NHW;
        float* __restrict__ o1 = o0 + (size_t)8 * HW2;
#pragma unroll
        for (int nt = 0; nt < 7; ++nt) {
            int w = nt * 8 + col0;
            *(float2*)(o0 + w) = make_float2(acc[mt][nt][0], acc[mt][nt][1]);
            *(float2*)(o1 + w) = make_float2(acc[mt][nt][2], acc[mt][nt][3]);
        }
    }
}

// ---------------------------------------------------------------------------
extern "C" void kernel_launch(void* const* d_in, const int* in_sizes, int n_in,
                              void* d_out, int out_size) {
    const float* x     = nullptr;
    const int*   label = nullptr;
    const float* base  = nullptr;
    const float* mask  = nullptr;
    for (int i = 0; i < n_in; ++i) {
        switch (in_sizes[i]) {
            case 25690112: x     = (const float*)d_in[i]; break;
            case 64:       label = (const int*)  d_in[i]; break;
            case 294912:   base  = (const float*)d_in[i]; break;
            case 4608:     mask  = (const float*)d_in[i]; break;
            default: break;
        }
    }
    if (!x     && n_in > 0) x     = (const float*)d_in[0];
    if (!label && n_in > 1) label = (const int*)  d_in[1];
    if (!base  && n_in > 2) base  = (const float*)d_in[2];
    if (!mask  && n_in > 3) mask  = (const float*)d_in[3];

    float* out = (float*)d_out;

    {
        const int total = NDG * 2 * 9 * 128 * 128;
        prep_weights_kernel<<<(total + 255) / 256, 256>>>(base, mask);
    }
    cudaFuncSetAttribute(adaconv_mma_kernel,
                         cudaFuncAttributeMaxDynamicSharedMemorySize, SMEM_TOTAL);
    {
        dim3 grid(14, 2, NB);
        adaconv_mma_kernel<<<grid, NTHREADS, SMEM_TOTAL>>>(x, label, out);
    }
}

// round 13
// speedup vs baseline: 1.8230x; 1.8230x over previous
#include <cuda_runtime.h>
#include <cuda_fp16.h>
#include <cstdint>
#include <cstddef>

#define NB   64
#define NIC  128
#define NOC  256
#define NHW  56
#define NDG  4
#define HW2  (NHW*NHW)

#define NTHREADS 256
#define BROWS 232                  // (2 out rows + 2 halo) x 58 w-positions

// ---------------- smem layout (dynamic, 106 KB -> 2 CTAs/SM) ----------------
#define SM_BH   0                  // 232 * 256 B = 59392
#define SM_A    59392              // 3 slots x 16 KB (A k-half slabs)
#define SMEM_TOTAL 108544

// Pre-swizzled fp16 weights, HALF-SLAB layout:
// per (d, octile, tap): [half(2)][oc(128)][128B swizzled] = 32 KB
__device__ __align__(16) __half g_w2[NDG * 2 * 9 * 16384];

// ---------------- ptx helpers (baseline ISA only) ----------------
__device__ __forceinline__ uint32_t smem_u32(const void* p) {
    uint32_t a;
    asm("{ .reg .u64 t; cvta.to.shared.u64 t, %1; cvt.u32.u64 %0, t; }"
        : "=r"(a) : "l"(p));
    return a;
}
__device__ __forceinline__ void ldsm_x4(uint32_t* r, uint32_t addr) {
    asm volatile("ldmatrix.sync.aligned.m8n8.x4.shared.b16 {%0,%1,%2,%3}, [%4];"
                 : "=r"(r[0]), "=r"(r[1]), "=r"(r[2]), "=r"(r[3]) : "r"(addr));
}
__device__ __forceinline__ void ldsm_x2(uint32_t* r, uint32_t addr) {
    asm volatile("ldmatrix.sync.aligned.m8n8.x2.shared.b16 {%0,%1}, [%2];"
                 : "=r"(r[0]), "=r"(r[1]) : "r"(addr));
}
__device__ __forceinline__ void cp_async16(uint32_t saddr, const void* gptr) {
    asm volatile("cp.async.cg.shared.global [%0], [%1], 16;"
                 :: "r"(saddr), "l"(gptr) : "memory");
}
#define CP_COMMIT() asm volatile("cp.async.commit_group;" ::: "memory")
#define CP_WAIT0()  asm volatile("cp.async.wait_group 0;" ::: "memory")

#define MMA_FP16(c, a, b)                                                     \
    asm volatile(                                                             \
        "mma.sync.aligned.m16n8k16.row.col.f32.f16.f16.f32 "                  \
        "{%0,%1,%2,%3},{%4,%5,%6,%7},{%8,%9},{%0,%1,%2,%3};"                  \
        : "+f"((c)[0]), "+f"((c)[1]), "+f"((c)[2]), "+f"((c)[3])              \
        : "r"((a)[0]), "r"((a)[1]), "r"((a)[2]), "r"((a)[3]),                 \
          "r"((b)[0]), "r"((b)[1]))

// ---------------------------------------------------------------------------
// Prep: masked weights -> fp16, half-slab swizzled image.
// byte = half*16384 + oc*128 + (((ic&63)*2) ^ ((oc&7)<<4)), half = ic>>6
// ---------------------------------------------------------------------------
__global__ void prep_weights_kernel(const float* __restrict__ base,
                                    const float* __restrict__ mask) {
    int e = blockIdx.x * blockDim.x + threadIdx.x;
    const int total = NDG * 2 * 9 * 128 * 128;
    if (e >= total) return;
    int ic  = e % 128;
    int t2  = e / 128;
    int oc  = t2 % 128;
    int t3  = t2 / 128;
    int tap = t3 % 9;
    int t4  = t3 / 9;
    int oct = t4 % 2;
    int d   = t4 / 2;

    float w = base[((size_t)(oct * 128 + oc) * 128 + ic) * 9 + tap] *
              mask[((size_t)d * 128 + ic) * 9 + tap];

    uint32_t byte = (uint32_t)((ic >> 6) * 16384 + oc * 128 +
                               (((ic & 63) * 2) ^ ((oc & 7) << 4)));
    size_t slab = (size_t)((d * 2 + oct) * 9 + tap) * 16384;
    g_w2[slab + (byte >> 1)] = __float2half(w);
}

// ---------------------------------------------------------------------------
// CTA = (row-pair hp, octile 128, b). 8 warps = 4 M-warps (32 oc) x 2 N-warps.
// A pipelined through a 3-slot 16KB half-slab ring; B built once. 2 CTAs/SM.
// ---------------------------------------------------------------------------
__global__ __launch_bounds__(NTHREADS, 2)
void adaconv_mma_kernel(const float* __restrict__ x,
                        const int*   __restrict__ label,
                        float*       __restrict__ out) {
    extern __shared__ char smem[];
    const uint32_t sb = smem_u32(smem);

    const int tid  = threadIdx.x;
    const int wid  = tid >> 5;
    const int lane = tid & 31;
    const int warp_m = wid & 3;       // oc tile of 32
    const int warp_n = wid >> 2;      // output row (0/1)

    const int hp  = blockIdx.x;       // 0..27
    const int oct = blockIdx.y;       // 0..1
    const int b   = blockIdx.z;       // 0..63
    const int h0  = hp * 2;

    int d = label[b];
    d = (d < 0) ? 0 : (d > NDG - 1 ? NDG - 1 : d);

    const float* __restrict__ xg = x + (size_t)b * NIC * HW2;
    const char* __restrict__ wbase =
        (const char*)(g_w2 + (size_t)((d * 2 + oct) * 9) * 16384);

    // ---- prologue: A(0).h0 -> slot0, A(0).h1 -> slot1 (1024 chunks each) ----
    {
#pragma unroll
        for (int j = 0; j < 4; ++j) {
            cp_async16(sb + SM_A + tid * 16 + j * 4096,
                       wbase + tid * 16 + j * 4096);
            cp_async16(sb + SM_A + 16384 + tid * 16 + j * 4096,
                       wbase + 16384 + tid * 16 + j * 4096);
        }
        CP_COMMIT();
    }

    // ---- build B once: thread tid owns n-row np=tid (<232), iterates ic ----
    if (tid < BROWS) {
        const int np   = tid;
        const int rowl = np / 58;
        const int wq   = np - rowl * 58;
        const int h_in = h0 - 1 + rowl;
        const int w_in = wq - 1;
        const bool inb = (h_in >= 0 && h_in < NHW && w_in >= 0 && w_in < NHW);
        const float* __restrict__ xp = xg + (size_t)h_in * NHW + w_in;
        const uint32_t brow = (uint32_t)(np * 256);
        const uint32_t bx   = (uint32_t)((np & 7) << 4);
#pragma unroll 8
        for (int icp = 0; icp < 64; ++icp) {
            float v0 = 0.f, v1 = 0.f;
            if (inb) {
                v0 = xp[(size_t)(icp * 2) * HW2];
                v1 = xp[(size_t)(icp * 2 + 1) * HW2];
            }
            __half h0b = __float2half(v0);
            __half h1b = __float2half(v1);
            uint32_t hw = (uint32_t)__half_as_ushort(h0b) |
                          ((uint32_t)__half_as_ushort(h1b) << 16);
            uint32_t byte = brow + (((uint32_t)(icp * 4)) ^ bx);
            *(uint32_t*)(smem + SM_BH + byte) = hw;
        }
    }

    float acc[2][7][4];
#pragma unroll
    for (int mt = 0; mt < 2; ++mt)
#pragma unroll
        for (int nt = 0; nt < 7; ++nt)
#pragma unroll
            for (int q = 0; q < 4; ++q) acc[mt][nt][q] = 0.f;

    const int arow     = warp_m * 32 + (lane & 15);
    const uint32_t akb = (uint32_t)((lane >> 4) << 4);

    uint32_t ah[2][2][4], bh[2][7][2];

    int cbase = 0;   // slot(t, h) = (cbase + h) % 3, cbase = (2t) % 3
    for (int tap = 0; tap < 9; ++tap) {
        const int dh = tap / 3, dw = tap % 3;
        const int nb = (warp_n + dh) * 58 + dw;
        const int s0 = cbase;
        const int s1 = (cbase + 1 == 3) ? 0 : cbase + 1;
        const int s2 = 3 - s0 - s1;
        const uint32_t a0 = sb + SM_A + (uint32_t)s0 * 16384;  // A(t).h0
        const uint32_t a1 = sb + SM_A + (uint32_t)s1 * 16384;  // A(t).h1

        CP_WAIT0();
        __syncthreads();   // A(t) halves + (tap==0: B) visible

        // issue A(tap+1).h0 into the free slot (hidden under the whole tap)
        if (tap < 8) {
            const char* gsrc = wbase + (size_t)(tap + 1) * 32768;
            uint32_t dst = sb + SM_A + (uint32_t)s2 * 16384;
#pragma unroll
            for (int j = 0; j < 4; ++j)
                cp_async16(dst + tid * 16 + j * 4096, gsrc + tid * 16 + j * 4096);
            CP_COMMIT();
        }

        auto load_frags = [&](int k, int s, uint32_t abase) {
            const uint32_t kb  = (uint32_t)(k * 32) + akb;          // B: full k
            const uint32_t kbl = (uint32_t)((k & 3) * 32) + akb;    // A: k-local
#pragma unroll
            for (int mt = 0; mt < 2; ++mt) {
                int r = arow + mt * 16;
                uint32_t off = (uint32_t)(r * 128) + (kbl ^ (uint32_t)((r & 7) << 4));
                ldsm_x4(ah[s][mt], abase + off);
            }
#pragma unroll
            for (int p = 0; p < 3; ++p) {
                int n = nb + p * 16 + (lane & 15);
                uint32_t off = (uint32_t)(n * 256) + (kb ^ (uint32_t)((n & 7) << 4));
                uint32_t t[4];
                ldsm_x4(t, sb + SM_BH + off);
                bh[s][2 * p][0] = t[0]; bh[s][2 * p][1] = t[2];
                bh[s][2 * p + 1][0] = t[1]; bh[s][2 * p + 1][1] = t[3];
            }
            {
                int n = nb + 48 + (lane & 7);
                uint32_t kb2 = (uint32_t)(k * 32) + (uint32_t)(((lane >> 3) & 1) << 4);
                uint32_t off = (uint32_t)(n * 256) + (kb2 ^ (uint32_t)((n & 7) << 4));
                uint32_t t[2];
                ldsm_x2(t, sb + SM_BH + off);
                bh[s][6][0] = t[0]; bh[s][6][1] = t[1];
            }
        };
        auto mma_block = [&](int s) {
#pragma unroll
            for (int mt = 0; mt < 2; ++mt)
#pragma unroll
                for (int nt = 0; nt < 7; ++nt) MMA_FP16(acc[mt][nt], ah[s][mt], bh[s][nt]);
        };

        // ---- k = 0..3 on slot s0, 2-deep pipelined ----
        load_frags(0, 0, a0);
#pragma unroll
        for (int k = 0; k < 4; ++k) {
            if (k < 3) load_frags(k + 1, (k + 1) & 1, a0);
            mma_block(k & 1);
        }

        __syncthreads();   // all warps done reading slot s0
        // issue A(tap+1).h1 into the now-dead slot s0 (hidden under k4-7)
        if (tap < 8) {
            const char* gsrc = wbase + (size_t)(tap + 1) * 32768 + 16384;
            uint32_t dst = sb + SM_A + (uint32_t)s0 * 16384;
#pragma unroll
            for (int j = 0; j < 4; ++j)
                cp_async16(dst + tid * 16 + j * 4096, gsrc + tid * 16 + j * 4096);
            CP_COMMIT();
        }

        // ---- k = 4..7 on slot s1, pipelined ----
        load_frags(4, 0, a1);
#pragma unroll
        for (int k = 4; k < 8; ++k) {
            if (k < 7) load_frags(k + 1, (k + 1) & 1, a1);
            mma_block(k & 1);
        }

        cbase += 2;
        if (cbase >= 3) cbase -= 3;
    }

    // ---- epilogue ----
    const int h = h0 + warp_n;
    const int col0 = (lane & 3) * 2;
    const int r0 = lane >> 2;
#pragma unroll
    for (int mt = 0; mt < 2; ++mt) {
        int ocb = oct * 128 + warp_m * 32 + mt * 16;
        float* __restrict__ o0 = out + ((size_t)b * NOC + ocb + r0) * HW2 + (size_t)h * NHW;
        float* __restrict__ o1 = o0 + (size_t)8 * HW2;
#pragma unroll
        for (int nt = 0; nt < 7; ++nt) {
            int w = nt * 8 + col0;
            *(float2*)(o0 + w) = make_float2(acc[mt][nt][0], acc[mt][nt][1]);
            *(float2*)(o1 + w) = make_float2(acc[mt][nt][2], acc[mt][nt][3]);
        }
    }
}

// ---------------------------------------------------------------------------
extern "C" void kernel_launch(void* const* d_in, const int* in_sizes, int n_in,
                              void* d_out, int out_size) {
    const float* x     = nullptr;
    const int*   label = nullptr;
    const float* base  = nullptr;
    const float* mask  = nullptr;
    for (int i = 0; i < n_in; ++i) {
        switch (in_sizes[i]) {
            case 25690112: x     = (const float*)d_in[i]; break;
            case 64:       label = (const int*)  d_in[i]; break;
            case 294912:   base  = (const float*)d_in[i]; break;
            case 4608:     mask  = (const float*)d_in[i]; break;
            default: break;
        }
    }
    if (!x     && n_in > 0) x     = (const float*)d_in[0];
    if (!label && n_in > 1) label = (const int*)  d_in[1];
    if (!base  && n_in > 2) base  = (const float*)d_in[2];
    if (!mask  && n_in > 3) mask  = (const float*)d_in[3];

    float* out = (float*)d_out;

    {
        const int total = NDG * 2 * 9 * 128 * 128;
        prep_weights_kernel<<<(total + 255) / 256, 256>>>(base, mask);
    }
    cudaFuncSetAttribute(adaconv_mma_kernel,
                         cudaFuncAttributeMaxDynamicSharedMemorySize, SMEM_TOTAL);
    {
        dim3 grid(28, 2, NB);
        adaconv_mma_kernel<<<grid, NTHREADS, SMEM_TOTAL>>>(x, label, out);
    }
}

// round 14
// speedup vs baseline: 1.8589x; 1.0197x over previous
#include <cuda_runtime.h>
#include <cuda_fp16.h>
#include <cstdint>
#include <cstddef>

#define NB   64
#define NIC  128
#define NOC  256
#define NHW  56
#define NDG  4
#define HW2  (NHW*NHW)

#define NTHREADS 256
#define BROWS 232                  // (2 out rows + 2 halo) x 58 w-positions

// ---------------- smem layout (dynamic, 106 KB -> 2 CTAs/SM) ----------------
#define SM_BH   0                  // 232 * 256 B = 59392
#define SM_A    59392              // 3 slots x 16 KB (A k-half slabs)
#define SMEM_TOTAL 108544

// Pre-swizzled fp16 weights, HALF-SLAB layout:
// per (d, octile, tap): [half(2)][oc(128)][128B swizzled] = 32 KB
__device__ __align__(16) __half g_w2[NDG * 2 * 9 * 16384];

// ---------------- ptx helpers (baseline ISA only) ----------------
__device__ __forceinline__ uint32_t smem_u32(const void* p) {
    uint32_t a;
    asm("{ .reg .u64 t; cvta.to.shared.u64 t, %1; cvt.u32.u64 %0, t; }"
        : "=r"(a) : "l"(p));
    return a;
}
__device__ __forceinline__ void ldsm_x4(uint32_t* r, uint32_t addr) {
    asm volatile("ldmatrix.sync.aligned.m8n8.x4.shared.b16 {%0,%1,%2,%3}, [%4];"
                 : "=r"(r[0]), "=r"(r[1]), "=r"(r[2]), "=r"(r[3]) : "r"(addr));
}
__device__ __forceinline__ void ldsm_x2(uint32_t* r, uint32_t addr) {
    asm volatile("ldmatrix.sync.aligned.m8n8.x2.shared.b16 {%0,%1}, [%2];"
                 : "=r"(r[0]), "=r"(r[1]) : "r"(addr));
}
__device__ __forceinline__ void cp_async16(uint32_t saddr, const void* gptr) {
    asm volatile("cp.async.cg.shared.global [%0], [%1], 16;"
                 :: "r"(saddr), "l"(gptr) : "memory");
}
#define CP_COMMIT() asm volatile("cp.async.commit_group;" ::: "memory")
#define CP_WAIT0()  asm volatile("cp.async.wait_group 0;" ::: "memory")

#define MMA_FP16(c, a, b)                                                     \
    asm volatile(                                                             \
        "mma.sync.aligned.m16n8k16.row.col.f32.f16.f16.f32 "                  \
        "{%0,%1,%2,%3},{%4,%5,%6,%7},{%8,%9},{%0,%1,%2,%3};"                  \
        : "+f"((c)[0]), "+f"((c)[1]), "+f"((c)[2]), "+f"((c)[3])              \
        : "r"((a)[0]), "r"((a)[1]), "r"((a)[2]), "r"((a)[3]),                 \
          "r"((b)[0]), "r"((b)[1]))

// ---------------------------------------------------------------------------
// Prep: masked weights -> fp16, half-slab swizzled image.
// byte = half*16384 + oc*128 + (((ic&63)*2) ^ ((oc&7)<<4)), half = ic>>6
// ---------------------------------------------------------------------------
__global__ void prep_weights_kernel(const float* __restrict__ base,
                                    const float* __restrict__ mask) {
    int e = blockIdx.x * blockDim.x + threadIdx.x;
    const int total = NDG * 2 * 9 * 128 * 128;
    if (e >= total) return;
    int ic  = e % 128;
    int t2  = e / 128;
    int oc  = t2 % 128;
    int t3  = t2 / 128;
    int tap = t3 % 9;
    int t4  = t3 / 9;
    int oct = t4 % 2;
    int d   = t4 / 2;

    float w = base[((size_t)(oct * 128 + oc) * 128 + ic) * 9 + tap] *
              mask[((size_t)d * 128 + ic) * 9 + tap];

    uint32_t byte = (uint32_t)((ic >> 6) * 16384 + oc * 128 +
                               (((ic & 63) * 2) ^ ((oc & 7) << 4)));
    size_t slab = (size_t)((d * 2 + oct) * 9 + tap) * 16384;
    g_w2[slab + (byte >> 1)] = __float2half(w);
}

// ---------------------------------------------------------------------------
// CTA = (row-pair hp, octile 128, b). 8 warps = 4 M-warps (32 oc) x 2 N-warps.
// A ring (3 x 16KB half-slabs), B built once, loads interleaved into the mma
// stream, tap order reversed on odd CTAs. 2 CTAs/SM.
// ---------------------------------------------------------------------------
__global__ __launch_bounds__(NTHREADS, 2)
void adaconv_mma_kernel(const float* __restrict__ x,
                        const int*   __restrict__ label,
                        float*       __restrict__ out) {
    extern __shared__ char smem[];
    const uint32_t sb = smem_u32(smem);

    const int tid  = threadIdx.x;
    const int wid  = tid >> 5;
    const int lane = tid & 31;
    const int warp_m = wid & 3;       // oc tile of 32
    const int warp_n = wid >> 2;      // output row (0/1)

    const int hp  = blockIdx.x;       // 0..27
    const int oct = blockIdx.y;       // 0..1
    const int b   = blockIdx.z;       // 0..63
    const int h0  = hp * 2;
    const int rev = blockIdx.x & 1;   // co-resident neighbors differ in x

    int d = label[b];
    d = (d < 0) ? 0 : (d > NDG - 1 ? NDG - 1 : d);

    const float* __restrict__ xg = x + (size_t)b * NIC * HW2;
    const char* __restrict__ wbase =
        (const char*)(g_w2 + (size_t)((d * 2 + oct) * 9) * 16384);

    const int tap0 = rev ? 8 : 0;

    // ---- prologue: A(tap0).h0 -> slot0, A(tap0).h1 -> slot1 ----
    {
        const char* g0 = wbase + (size_t)tap0 * 32768;
#pragma unroll
        for (int j = 0; j < 4; ++j) {
            cp_async16(sb + SM_A + tid * 16 + j * 4096, g0 + tid * 16 + j * 4096);
            cp_async16(sb + SM_A + 16384 + tid * 16 + j * 4096,
                       g0 + 16384 + tid * 16 + j * 4096);
        }
        CP_COMMIT();
    }

    // ---- build B once ----
    if (tid < BROWS) {
        const int np   = tid;
        const int rowl = np / 58;
        const int wq   = np - rowl * 58;
        const int h_in = h0 - 1 + rowl;
        const int w_in = wq - 1;
        const bool inb = (h_in >= 0 && h_in < NHW && w_in >= 0 && w_in < NHW);
        const float* __restrict__ xp = xg + (size_t)h_in * NHW + w_in;
        const uint32_t brow = (uint32_t)(np * 256);
        const uint32_t bx   = (uint32_t)((np & 7) << 4);
#pragma unroll 8
        for (int icp = 0; icp < 64; ++icp) {
            float v0 = 0.f, v1 = 0.f;
            if (inb) {
                v0 = xp[(size_t)(icp * 2) * HW2];
                v1 = xp[(size_t)(icp * 2 + 1) * HW2];
            }
            __half h0b = __float2half(v0);
            __half h1b = __float2half(v1);
            uint32_t hw = (uint32_t)__half_as_ushort(h0b) |
                          ((uint32_t)__half_as_ushort(h1b) << 16);
            uint32_t byte = brow + (((uint32_t)(icp * 4)) ^ bx);
            *(uint32_t*)(smem + SM_BH + byte) = hw;
        }
    }

    float acc[2][7][4];
#pragma unroll
    for (int mt = 0; mt < 2; ++mt)
#pragma unroll
        for (int nt = 0; nt < 7; ++nt)
#pragma unroll
            for (int q = 0; q < 4; ++q) acc[mt][nt][q] = 0.f;

    // ---- hoisted per-warp invariants ----
    const int arow     = warp_m * 32 + (lane & 15);
    const uint32_t akb = (uint32_t)((lane >> 4) << 4);
    // A: per-mt byte base & swizzle-x (tap-invariant)
    uint32_t aoff[2], ax[2];
#pragma unroll
    for (int mt = 0; mt < 2; ++mt) {
        int r = arow + mt * 16;
        aoff[mt] = (uint32_t)(r * 128);
        ax[mt]   = (uint32_t)((r & 7) << 4);
    }
    const uint32_t l15 = (uint32_t)(lane & 15);
    const uint32_t l7  = (uint32_t)(lane & 7);
    const uint32_t akb2 = (uint32_t)(((lane >> 3) & 1) << 4);

    uint32_t ah[2][2][4], bh[2][7][2];

    int cbase = 0;   // slot(i,h) = (cbase + h) % 3
    for (int it = 0; it < 9; ++it) {
        const int tap  = rev ? 8 - it : it;
        const int ntap = rev ? tap - 1 : tap + 1;   // next tap (valid if it<8)
        const int dh = tap / 3, dw = tap % 3;
        const int nb = (warp_n + dh) * 58 + dw;

        // B bases for this tap (single bx thanks to p*16 % 8 == 0)
        const uint32_t bxx   = (uint32_t)(((nb + (lane & 7)) & 7) << 4);
        const uint32_t boff0 = sb + SM_BH + (uint32_t)((nb + l15) * 256);
        const uint32_t boff1 = boff0 + 16 * 256;
        const uint32_t boff2 = boff0 + 32 * 256;
        const uint32_t boff6 = sb + SM_BH + (uint32_t)((nb + 48 + l7) * 256);

        const int s0 = cbase;
        const int s1 = (cbase + 1 == 3) ? 0 : cbase + 1;
        const int s2 = 3 - s0 - s1;
        const uint32_t a0 = sb + SM_A + (uint32_t)s0 * 16384;  // A(tap).h0
        const uint32_t a1 = sb + SM_A + (uint32_t)s1 * 16384;  // A(tap).h1

        CP_WAIT0();
        __syncthreads();

        if (it < 8) {   // A(ntap).h0 into free slot, hidden under k0-7
            const char* gsrc = wbase + (size_t)ntap * 32768;
            uint32_t dst = sb + SM_A + (uint32_t)s2 * 16384;
#pragma unroll
            for (int j = 0; j < 4; ++j)
                cp_async16(dst + tid * 16 + j * 4096, gsrc + tid * 16 + j * 4096);
            CP_COMMIT();
        }

        // ---- per-frag loaders (addresses from hoisted bases) ----
        auto la = [&](int mt, int s, uint32_t abase, int k) {
            uint32_t kbl = (uint32_t)((k & 3) * 32) + akb;
            ldsm_x4(ah[s][mt], abase + aoff[mt] + (kbl ^ ax[mt]));
        };
        auto lb4 = [&](int p, int s, int k) {
            uint32_t kb = (uint32_t)(k * 32) + akb;
            uint32_t addr = (p == 0 ? boff0 : (p == 1 ? boff1 : boff2)) + (kb ^ bxx);
            uint32_t t[4];
            ldsm_x4(t, addr);
            bh[s][2 * p][0] = t[0]; bh[s][2 * p][1] = t[2];
            bh[s][2 * p + 1][0] = t[1]; bh[s][2 * p + 1][1] = t[3];
        };
        auto lb2 = [&](int s, int k) {
            uint32_t kb2 = (uint32_t)(k * 32) + akb2;
            uint32_t t[2];
            ldsm_x2(t, boff6 + (kb2 ^ bxx));
            bh[s][6][0] = t[0]; bh[s][6][1] = t[1];
        };
        // round(k): mma of buffer s interleaved with loads for k+1 into s^1
        auto round = [&](int k, uint32_t a_next, bool do_load) {
            const int s = k & 1, ns = s ^ 1;
            const int kn = k + 1;
            if (do_load) { la(0, ns, a_next, kn); la(1, ns, a_next, kn); }
            MMA_FP16(acc[0][0], ah[s][0], bh[s][0]);
            MMA_FP16(acc[0][1], ah[s][0], bh[s][1]);
            if (do_load) lb4(0, ns, kn);
            MMA_FP16(acc[0][2], ah[s][0], bh[s][2]);
            MMA_FP16(acc[0][3], ah[s][0], bh[s][3]);
            if (do_load) lb4(1, ns, kn);
            MMA_FP16(acc[0][4], ah[s][0], bh[s][4]);
            MMA_FP16(acc[0][5], ah[s][0], bh[s][5]);
            if (do_load) lb4(2, ns, kn);
            MMA_FP16(acc[0][6], ah[s][0], bh[s][6]);
            MMA_FP16(acc[1][0], ah[s][1], bh[s][0]);
            if (do_load) lb2(ns, kn);
            MMA_FP16(acc[1][1], ah[s][1], bh[s][1]);
            MMA_FP16(acc[1][2], ah[s][1], bh[s][2]);
            MMA_FP16(acc[1][3], ah[s][1], bh[s][3]);
            MMA_FP16(acc[1][4], ah[s][1], bh[s][4]);
            MMA_FP16(acc[1][5], ah[s][1], bh[s][5]);
            MMA_FP16(acc[1][6], ah[s][1], bh[s][6]);
        };

        // ---- k0..3 on slot s0 ----
        la(0, 0, a0, 0); la(1, 0, a0, 0);
        lb4(0, 0, 0); lb4(1, 0, 0); lb4(2, 0, 0); lb2(0, 0);
#pragma unroll
        for (int k = 0; k < 3; ++k) round(k, a0, true);
        round(3, a1, true);          // loads k4 from h1 slab

        __syncthreads();             // slot s0 dead; cp target recyclable
        if (it < 8) {                // A(ntap).h1 into s0, hidden under k4-7
            const char* gsrc = wbase + (size_t)ntap * 32768 + 16384;
            uint32_t dst = sb + SM_A + (uint32_t)s0 * 16384;
#pragma unroll
            for (int j = 0; j < 4; ++j)
                cp_async16(dst + tid * 16 + j * 4096, gsrc + tid * 16 + j * 4096);
            CP_COMMIT();
        }

        // ---- k4..7 on slot s1 ----
#pragma unroll
        for (int k = 4; k < 7; ++k) round(k, a1, true);
        round(7, a1, false);

        cbase += 2;
        if (cbase >= 3) cbase -= 3;
    }

    // ---- epilogue ----
    const int h = h0 + warp_n;
    const int col0 = (lane & 3) * 2;
    const int r0 = lane >> 2;
#pragma unroll
    for (int mt = 0; mt < 2; ++mt) {
        int ocb = oct * 128 + warp_m * 32 + mt * 16;
        float* __restrict__ o0 = out + ((size_t)b * NOC + ocb + r0) * HW2 + (size_t)h * NHW;
        float* __restrict__ o1 = o0 + (size_t)8 * HW2;
#pragma unroll
        for (int nt = 0; nt < 7; ++nt) {
            int w = nt * 8 + col0;
            *(float2*)(o0 + w) = make_float2(acc[mt][nt][0], acc[mt][nt][1]);
            *(float2*)(o1 + w) = make_float2(acc[mt][nt][2], acc[mt][nt][3]);
        }
    }
}

// ---------------------------------------------------------------------------
extern "C" void kernel_launch(void* const* d_in, const int* in_sizes, int n_in,
                              void* d_out, int out_size) {
    const float* x     = nullptr;
    const int*   label = nullptr;
    const float* base  = nullptr;
    const float* mask  = nullptr;
    for (int i = 0; i < n_in; ++i) {
        switch (in_sizes[i]) {
            case 25690112: x     = (const float*)d_in[i]; break;
            case 64:       label = (const int*)  d_in[i]; break;
            case 294912:   base  = (const float*)d_in[i]; break;
            case 4608:     mask  = (const float*)d_in[i]; break;
            default: break;
        }
    }
    if (!x     && n_in > 0) x     = (const float*)d_in[0];
    if (!label && n_in > 1) label = (const int*)  d_in[1];
    if (!base  && n_in > 2) base  = (const float*)d_in[2];
    if (!mask  && n_in > 3) mask  = (const float*)d_in[3];

    float* out = (float*)d_out;

    {
        const int total = NDG * 2 * 9 * 128 * 128;
        prep_weights_kernel<<<(total + 255) / 256, 256>>>(base, mask);
    }
    cudaFuncSetAttribute(adaconv_mma_kernel,
                         cudaFuncAttributeMaxDynamicSharedMemorySize, SMEM_TOTAL);
    {
        dim3 grid(28, 2, NB);
        adaconv_mma_kernel<<<grid, NTHREADS, SMEM_TOTAL>>>(x, label, out);
    }
}